// round 4
// baseline (speedup 1.0000x reference)
#include <cuda_runtime.h>
#include <math.h>

#define IM_FE_RATIO 16.0f
#define TPB 256
#define FLOATS_PER_THREAD 16
#define CHUNK (TPB * FLOATS_PER_THREAD)   // 4096 floats per block

// Fused kernel: grid is (blocksPerRow, rows). Each block zero-fills a
// 4096-float chunk of one (b,n) row's HW plane with float4 stores; threads
// whose addresses intersect the row's 6x6 blurred bilinear patch write the
// patch values instead of zeros.
__global__ void __launch_bounds__(TPB) inver_interp_fused(
    const float* __restrict__ Xg,
    const float* __restrict__ kp,
    const float* __restrict__ gk,
    float* __restrict__ out,
    int N, int H, int W, int HW)
{
    const int row   = blockIdx.y;    // 0 .. B*N-1
    const int chunk = blockIdx.x;    // 0 .. blocksPerRow-1
    const int t     = threadIdx.x;

    __shared__ float s_gk[25];
    __shared__ float s_pf[4];   // upx, lwx, upy, lwy
    __shared__ int   s_pi[5];   // valid, x0, y0, ox1, oy1

    // warp 1 stages the 5x5 gaussian kernel (identical per channel)
    if (t >= 32 && t < 57) s_gk[t - 32] = gk[t - 32];

    // warp 0: one-hot gather reduction over N (N <= 32)
    if (t < 32) {
        const int b = row / N;
        float xg = 0.f, kx = 0.f, ky = 0.f;
        if (t < N) {
            xg = Xg[(size_t)row * N + t];
            const float* k2 = kp + ((size_t)(b * N + t)) * 2;
            kx = xg * k2[0];
            ky = xg * k2[1];
        }
        #pragma unroll
        for (int off = 16; off > 0; off >>= 1) {
            xg += __shfl_xor_sync(0xffffffffu, xg, off);
            kx += __shfl_xor_sync(0xffffffffu, kx, off);
            ky += __shfl_xor_sync(0xffffffffu, ky, off);
        }
        if (t == 0) {
            if (xg == 0.0f) {
                s_pi[0] = 0;
            } else {
                const float x = kx * (1.0f / IM_FE_RATIO) - 0.5f;
                const float y = ky * (1.0f / IM_FE_RATIO) - 0.5f;
                const float maxx = (float)(W - 1);
                const float maxy = (float)(H - 1);
                const float lox = fminf(fmaxf(floorf(x), 0.0f), maxx);
                const float hix = fminf(fmaxf(ceilf(x),  0.0f), maxx);
                const float loy = fminf(fmaxf(floorf(y), 0.0f), maxy);
                const float hiy = fminf(fmaxf(ceilf(y),  0.0f), maxy);
                s_pi[0] = 1;
                s_pi[1] = (int)lox;                 // x0
                s_pi[2] = (int)loy;                 // y0
                s_pi[3] = (int)hix - (int)lox;      // ox1 (0 or 1)
                s_pi[4] = (int)hiy - (int)loy;      // oy1 (0 or 1)
                s_pf[0] = x - lox;                  // upx
                s_pf[1] = 1.0f - (x - lox);         // lwx
                s_pf[2] = y - loy;                  // upy
                s_pf[3] = 1.0f - (y - loy);         // lwy
            }
        }
    }
    __syncthreads();

    float* __restrict__ rowout = out + (size_t)row * HW;
    const int base  = chunk * CHUNK + t * FLOATS_PER_THREAD;
    const int valid = s_pi[0];

    // Fast path: W%4==0 and chunk fully inside the plane -> no bound checks.
    if (((W & 3) == 0) && (chunk * CHUNK + CHUNK <= HW)) {
        if (!valid) {
            #pragma unroll
            for (int g = 0; g < 4; g++)
                *(float4*)(rowout + base + g * 4) = make_float4(0.f, 0.f, 0.f, 0.f);
            return;
        }
        const int x0 = s_pi[1], y0 = s_pi[2], ox1 = s_pi[3], oy1 = s_pi[4];
        const float upx = s_pf[0], lwx = s_pf[1], upy = s_pf[2], lwy = s_pf[3];
        const int py0 = y0 - 2, px0 = x0 - 2;

        #pragma unroll
        for (int g = 0; g < 4; g++) {
            const int f  = base + g * 4;
            const int py = f / W;
            const int px = f - py * W;
            float4 v = make_float4(0.f, 0.f, 0.f, 0.f);
            if ((unsigned)(py - py0) <= 5u && px + 3 >= px0 && px <= px0 + 5) {
                const int dy = py - py0;
                float vv[4];
                #pragma unroll
                for (int e = 0; e < 4; e++) {
                    const int dx = px + e - px0;
                    float val = 0.f;
                    if ((unsigned)dx <= 5u) {
                        #pragma unroll
                        for (int cy = 0; cy < 2; cy++) {
                            const int   oy = cy ? oy1 : 0;
                            const float wy = cy ? upy : lwy;
                            const int   ki = dy - oy;
                            if (ki < 0 || ki > 4) continue;
                            #pragma unroll
                            for (int cx = 0; cx < 2; cx++) {
                                const int   ox = cx ? ox1 : 0;
                                const float wx = cx ? upx : lwx;
                                const int   kj = dx - ox;
                                if (kj < 0 || kj > 4) continue;
                                val += (wy * wx) * s_gk[ki * 5 + kj];
                            }
                        }
                    }
                    vv[e] = val;
                }
                v = make_float4(vv[0], vv[1], vv[2], vv[3]);
            }
            *(float4*)(rowout + f) = v;
        }
    } else {
        // generic scalar fallback (tail chunk or W not multiple of 4)
        const int x0 = s_pi[1], y0 = s_pi[2], ox1 = s_pi[3], oy1 = s_pi[4];
        const float upx = s_pf[0], lwx = s_pf[1], upy = s_pf[2], lwy = s_pf[3];
        const int py0 = y0 - 2, px0 = x0 - 2;
        for (int e = 0; e < FLOATS_PER_THREAD; e++) {
            const int f = base + e;
            if (f >= HW) break;
            float val = 0.f;
            if (valid) {
                const int py = f / W;
                const int px = f - py * W;
                const int dy = py - py0;
                const int dx = px - px0;
                if ((unsigned)dy <= 5u && (unsigned)dx <= 5u) {
                    #pragma unroll
                    for (int cy = 0; cy < 2; cy++) {
                        const int   oy = cy ? oy1 : 0;
                        const float wy = cy ? upy : lwy;
                        const int   ki = dy - oy;
                        if (ki < 0 || ki > 4) continue;
                        #pragma unroll
                        for (int cx = 0; cx < 2; cx++) {
                            const int   ox = cx ? ox1 : 0;
                            const float wx = cx ? upx : lwx;
                            const int   kj = dx - ox;
                            if (kj < 0 || kj > 4) continue;
                            val += (wy * wx) * s_gk[ki * 5 + kj];
                        }
                    }
                }
            }
            rowout[f] = val;
        }
    }
}

extern "C" void kernel_launch(void* const* d_in, const int* in_sizes, int n_in,
                              void* d_out, int out_size) {
    const float* Xg = (const float*)d_in[0];   // (B, N, N)
    const float* kp = (const float*)d_in[1];   // (B, N, 2)
    const float* gk = (const float*)d_in[2];   // (N, 1, 5, 5)

    const int rows = in_sizes[1] / 2;          // B*N
    const int N    = in_sizes[0] / rows;       // N (square one-hot)
    const int HW   = out_size / rows;          // H*W
    int W = (int)(sqrt((double)HW) + 0.5);
    int H = HW / W;

    const int blocksPerRow = (HW + CHUNK - 1) / CHUNK;
    dim3 grid(blocksPerRow, rows);

    inver_interp_fused<<<grid, TPB>>>(Xg, kp, gk, (float*)d_out, N, H, W, HW);
}

// round 7
// speedup vs baseline: 1.0589x; 1.0589x over previous
#include <cuda_runtime.h>
#include <math.h>

#define IM_FE_RATIO 16.0f
#define TPB 256
#define FPT 16                    // floats per thread
#define CHUNK (TPB * FPT)         // 4096 floats per block

// Fused zero-fill + blurred-bilinear-patch scatter.
// grid = (chunksPerPlane, N, B). Block (c, i, b) fills floats
// [c*CHUNK, (c+1)*CHUNK) of plane row = b*N+i. Per-WARP ballot/shfl prologue
// (no shared memory, no __syncthreads); patch math only in the ~2% of warps
// whose image rows intersect the 6x6 patch.
__global__ void __launch_bounds__(TPB) inver_interp_fused2(
    const float* __restrict__ Xg,
    const float* __restrict__ kp,
    const float* __restrict__ gk,
    float* __restrict__ out,
    int N, int H, int W, int HW, int wshift)
{
    const int b     = blockIdx.z;
    const int row   = b * N + blockIdx.y;
    const int chunk = blockIdx.x;
    const int t     = threadIdx.x;
    const int lane  = t & 31;

    // ---- per-warp one-hot gather: Xg row has at most one 1.0 ----
    const unsigned FULL = 0xffffffffu;
    float xg = 0.f, kxv = 0.f, kyv = 0.f;
    if (lane < N) {
        xg = Xg[(size_t)row * N + lane];
        const float2 k2 = ((const float2*)kp)[(size_t)b * N + lane];
        kxv = k2.x; kyv = k2.y;
    }
    const unsigned bal = __ballot_sync(FULL, xg != 0.f);
    const bool valid = (bal != 0u);
    const int  j  = valid ? (__ffs(bal) - 1) : 0;
    const float mx = __shfl_sync(FULL, xg,  j);          // == mask (0/1)
    const float kx = __shfl_sync(FULL, kxv, j) * mx;     // = sum(Xg*kp).x
    const float ky = __shfl_sync(FULL, kyv, j) * mx;

    const int fBase   = chunk * CHUNK + t * FPT;         // first float of thread
    float* __restrict__ rowout = out + (size_t)row * HW;

    int y0 = 0, x0 = 0, ox1 = 0, oy1 = 0;
    float upx = 0.f, lwx = 0.f, upy = 0.f, lwy = 0.f;
    bool inter = false;

    if (valid) {
        const float x = kx * (1.0f / IM_FE_RATIO) - 0.5f;
        const float y = ky * (1.0f / IM_FE_RATIO) - 0.5f;
        const float maxx = (float)(W - 1);
        const float maxy = (float)(H - 1);
        const float lox = fminf(fmaxf(floorf(x), 0.0f), maxx);
        const float hix = fminf(fmaxf(ceilf(x),  0.0f), maxx);
        const float loy = fminf(fmaxf(floorf(y), 0.0f), maxy);
        const float hiy = fminf(fmaxf(ceilf(y),  0.0f), maxy);
        x0 = (int)lox; y0 = (int)loy;
        ox1 = (int)hix - x0; oy1 = (int)hiy - y0;
        upx = x - lox; lwx = 1.0f - upx;
        upy = y - loy; lwy = 1.0f - upy;

        // warp-uniform intersection: warp covers floats [wf, wf+512)
        const int wf  = chunk * CHUNK + (t & ~31) * FPT;
        if (wshift >= 0) {
            const int rLo = wf >> wshift;
            const int rHi = (wf + 32 * FPT - 1) >> wshift;
            inter = (y0 - 2 <= rHi) && (y0 + 3 >= rLo);
        } else {
            const int rLo = wf / W;
            const int rHi = (wf + 32 * FPT - 1) / W;
            inter = (y0 - 2 <= rHi) && (y0 + 3 >= rLo);
        }
    }

    // ---- fast path: full chunk, no bounds checks ----
    if (fBase + FPT <= HW) {
        if (!inter) {
            // pure streaming zero-fill: 4 independent STG.128
            #pragma unroll
            for (int g = 0; g < 4; g++)
                *(float4*)(rowout + fBase + g * 4) =
                    make_float4(0.f, 0.f, 0.f, 0.f);
            return;
        }
        // patch warp: thread's 16 floats lie in one image row (16 | W, W pow2)
        int py, px;
        if (wshift >= 0) { py = fBase >> wshift; px = fBase & (W - 1); }
        else             { py = fBase / W;       px = fBase - py * W;  }
        const int dy = py - (y0 - 2);
        float v[16];
        #pragma unroll
        for (int e = 0; e < 16; e++) v[e] = 0.f;
        if ((unsigned)dy <= 5u) {
            #pragma unroll
            for (int e = 0; e < 16; e++) {
                const int dx = px + e - (x0 - 2);
                if ((unsigned)dx <= 5u) {
                    float val = 0.f;
                    #pragma unroll
                    for (int cy = 0; cy < 2; cy++) {
                        const int   oy = cy ? oy1 : 0;
                        const float wy = cy ? upy : lwy;
                        const int   ki = dy - oy;
                        if (ki < 0 || ki > 4) continue;
                        #pragma unroll
                        for (int cx = 0; cx < 2; cx++) {
                            const int   ox = cx ? ox1 : 0;
                            const float wx = cx ? upx : lwx;
                            const int   kj = dx - ox;
                            if (kj < 0 || kj > 4) continue;
                            val += (wy * wx) * __ldg(gk + ki * 5 + kj);
                        }
                    }
                    v[e] = val * mx;   // * mask (== 1.0 when valid)
                }
            }
        }
        #pragma unroll
        for (int g = 0; g < 4; g++)
            *(float4*)(rowout + fBase + g * 4) =
                make_float4(v[g*4], v[g*4+1], v[g*4+2], v[g*4+3]);
        return;
    }

    // ---- generic tail path (partial chunk) ----
    for (int e = 0; e < FPT; e++) {
        const int f = fBase + e;
        if (f >= HW) break;
        float val = 0.f;
        if (inter) {
            int py, px;
            if (wshift >= 0) { py = f >> wshift; px = f & (W - 1); }
            else             { py = f / W;       px = f - py * W;  }
            const int dy = py - (y0 - 2);
            const int dx = px - (x0 - 2);
            if ((unsigned)dy <= 5u && (unsigned)dx <= 5u) {
                #pragma unroll
                for (int cy = 0; cy < 2; cy++) {
                    const int   oy = cy ? oy1 : 0;
                    const float wy = cy ? upy : lwy;
                    const int   ki = dy - oy;
                    if (ki < 0 || ki > 4) continue;
                    #pragma unroll
                    for (int cx = 0; cx < 2; cx++) {
                        const int   ox = cx ? ox1 : 0;
                        const float wx = cx ? upx : lwx;
                        const int   kj = dx - ox;
                        if (kj < 0 || kj > 4) continue;
                        val += (wy * wx) * __ldg(gk + ki * 5 + kj);
                    }
                }
                val *= mx;
            }
        }
        rowout[f] = val;
    }
}

extern "C" void kernel_launch(void* const* d_in, const int* in_sizes, int n_in,
                              void* d_out, int out_size) {
    const float* Xg = (const float*)d_in[0];   // (B, N, N)
    const float* kp = (const float*)d_in[1];   // (B, N, 2)
    const float* gk = (const float*)d_in[2];   // (N, 1, 5, 5)

    const int rows = in_sizes[1] / 2;          // B*N
    const int N    = in_sizes[0] / rows;       // N (square one-hot)
    const int B    = rows / N;
    const int HW   = out_size / rows;          // H*W
    int W = (int)(sqrt((double)HW) + 0.5);
    int H = HW / W;

    int wshift = -1;
    if ((W & (W - 1)) == 0) {                  // power of two
        wshift = 0;
        while ((1 << wshift) != W) wshift++;
    }

    const int chunksPerPlane = (HW + CHUNK - 1) / CHUNK;
    dim3 grid(chunksPerPlane, N, B);

    inver_interp_fused2<<<grid, TPB>>>(Xg, kp, gk, (float*)d_out,
                                       N, H, W, HW, wshift);
}

// round 9
// speedup vs baseline: 1.3472x; 1.2722x over previous
#include <cuda_runtime.h>
#include <stdint.h>
#include <math.h>

#define IM_FE_RATIO 16.0f
#define TPB 256
#define CHUNK_FLOATS 4096                 // 16 KB per bulk copy
#define CHUNK_BYTES (CHUNK_FLOATS * 4)

static __device__ __forceinline__ uint32_t smem_u32(const void* p) {
    uint32_t a;
    asm("{ .reg .u64 t; cvta.to.shared.u64 t, %1; cvt.u32.u64 %0, t; }"
        : "=r"(a) : "l"(p));
    return a;
}

// One block per (b,n) plane. Three immutable smem buffers built once:
//   bufZ  = zeros, bufP0/bufP1 = zeros + patch cells for the <=2 chunks the
// 6-row blurred patch can straddle. Then t0 streams the whole plane to global
// with back-to-back cp.async.bulk copies (async-proxy stores bypass the
// L1tex STG path that capped earlier attempts at ~2.2 TB/s). No buffer is
// ever written after any copy starts -> race-free by construction.
__global__ void __launch_bounds__(TPB) inver_interp_bulk2(
    const float* __restrict__ Xg,
    const float* __restrict__ kp,
    const float* __restrict__ gk,
    float* __restrict__ out,
    int N, int H, int W, int HW)
{
    __shared__ float bufZ[CHUNK_FLOATS];
    __shared__ float bufP0[CHUNK_FLOATS];
    __shared__ float bufP1[CHUNK_FLOATS];

    const int row  = blockIdx.x;          // b*N + i
    const int b    = row / N;
    const int t    = threadIdx.x;
    const int lane = t & 31;

    // ---- per-warp ballot prologue (Xg row is one-hot or all-zero) ----
    const unsigned FULL = 0xffffffffu;
    float xg = 0.f, kxv = 0.f, kyv = 0.f;
    if (lane < N) {
        xg = Xg[(size_t)row * N + lane];
        const float2 k2 = ((const float2*)kp)[(size_t)b * N + lane];
        kxv = k2.x; kyv = k2.y;
    }
    const unsigned bal = __ballot_sync(FULL, xg != 0.f);
    const bool valid = (bal != 0u);
    const int  j  = valid ? (__ffs(bal) - 1) : 0;
    const float mx = __shfl_sync(FULL, xg,  j);          // mask (0/1)
    const float kx = __shfl_sync(FULL, kxv, j) * mx;
    const float ky = __shfl_sync(FULL, kyv, j) * mx;

    int x0 = 0, y0 = 0, ox1 = 0, oy1 = 0;
    float upx = 0.f, lwx = 0.f, upy = 0.f, lwy = 0.f;
    int cLo = -1, cHi = -1;               // no patch chunks by default
    if (valid) {
        const float x = kx * (1.0f / IM_FE_RATIO) - 0.5f;
        const float y = ky * (1.0f / IM_FE_RATIO) - 0.5f;
        const float maxx = (float)(W - 1);
        const float maxy = (float)(H - 1);
        const float lox = fminf(fmaxf(floorf(x), 0.0f), maxx);
        const float hix = fminf(fmaxf(ceilf(x),  0.0f), maxx);
        const float loy = fminf(fmaxf(floorf(y), 0.0f), maxy);
        const float hiy = fminf(fmaxf(ceilf(y),  0.0f), maxy);
        x0 = (int)lox; y0 = (int)loy;
        ox1 = (int)hix - x0; oy1 = (int)hiy - y0;
        upx = x - lox; lwx = 1.0f - upx;
        upy = y - loy; lwy = 1.0f - upy;
        const int pyMin = max(0, y0 - 2), pyMax = min(H - 1, y0 + 3);
        const int pxMin = max(0, x0 - 2), pxMax = min(W - 1, x0 + 3);
        cLo = (pyMin * W + pxMin) / CHUNK_FLOATS;
        cHi = (pyMax * W + pxMax) / CHUNK_FLOATS;
    }

    // ---- zero all three buffers ----
    #pragma unroll
    for (int i = t * 4; i < CHUNK_FLOATS; i += TPB * 4) {
        *(float4*)(bufZ  + i) = make_float4(0.f, 0.f, 0.f, 0.f);
        *(float4*)(bufP0 + i) = make_float4(0.f, 0.f, 0.f, 0.f);
        *(float4*)(bufP1 + i) = make_float4(0.f, 0.f, 0.f, 0.f);
    }
    __syncthreads();

    // ---- write patch cells (one per thread t<36) into bufP0/bufP1 ----
    if (valid && t < 36) {
        const int dy = t / 6, dx = t - dy * 6;
        const int py = y0 - 2 + dy, px = x0 - 2 + dx;
        if (py >= 0 && py < H && px >= 0 && px < W) {
            float val = 0.f;
            #pragma unroll
            for (int cy = 0; cy < 2; cy++) {
                const int   oy = cy ? oy1 : 0;
                const float wy = cy ? upy : lwy;
                const int   ki = dy - oy;
                if (ki < 0 || ki > 4) continue;
                #pragma unroll
                for (int cx = 0; cx < 2; cx++) {
                    const int   ox = cx ? ox1 : 0;
                    const float wx = cx ? upx : lwx;
                    const int   kj = dx - ox;
                    if (kj < 0 || kj > 4) continue;
                    val += (wy * wx) * __ldg(gk + ki * 5 + kj);
                }
            }
            const int idx = py * W + px;
            const int c   = idx / CHUNK_FLOATS;
            if (c == cLo)      bufP0[idx - cLo * CHUNK_FLOATS] = val;
            else if (c == cHi) bufP1[idx - cHi * CHUNK_FLOATS] = val;
        }
    }
    __syncthreads();

    // ---- stream plane to global: back-to-back bulk copies, no mid waits ----
    if (t == 0) {
        const uint32_t sZ  = smem_u32(bufZ);
        const uint32_t sP0 = smem_u32(bufP0);
        const uint32_t sP1 = smem_u32(bufP1);
        float* __restrict__ rowout = out + (size_t)row * HW;
        const int nChunks = (HW + CHUNK_FLOATS - 1) / CHUNK_FLOATS;

        asm volatile("fence.proxy.async.shared::cta;" ::: "memory");
        for (int c = 0; c < nChunks; c++) {
            const int cbase  = c * CHUNK_FLOATS;
            const int cbytes = min(CHUNK_FLOATS, HW - cbase) * 4;
            const uint32_t src = (c == cLo) ? sP0 : (c == cHi) ? sP1 : sZ;
            asm volatile(
                "cp.async.bulk.global.shared::cta.bulk_group [%0], [%1], %2;"
                :: "l"(rowout + cbase), "r"(src), "r"((uint32_t)cbytes)
                : "memory");
        }
        asm volatile("cp.async.bulk.commit_group;" ::: "memory");
        asm volatile("cp.async.bulk.wait_group.read 0;" ::: "memory");
    }
    __syncthreads();   // smem must outlive async reads for all threads
}

extern "C" void kernel_launch(void* const* d_in, const int* in_sizes, int n_in,
                              void* d_out, int out_size) {
    const float* Xg = (const float*)d_in[0];   // (B, N, N)
    const float* kp = (const float*)d_in[1];   // (B, N, 2)
    const float* gk = (const float*)d_in[2];   // (N, 1, 5, 5)

    const int rows = in_sizes[1] / 2;          // B*N
    const int N    = in_sizes[0] / rows;       // N (square one-hot)
    const int HW   = out_size / rows;          // H*W
    int W = (int)(sqrt((double)HW) + 0.5);
    int H = HW / W;

    inver_interp_bulk2<<<rows, TPB>>>(Xg, kp, gk, (float*)d_out, N, H, W, HW);
}

// round 12
// speedup vs baseline: 1.5189x; 1.1274x over previous
#include <cuda_runtime.h>
#include <stdint.h>
#include <math.h>

#define IM_FE_RATIO 16.0f
#define TPB 256
#define CHUNK_FLOATS 8192                 // 32 KB per CTA / per bulk copy

static __device__ __forceinline__ uint32_t smem_u32(const void* p) {
    uint32_t a;
    asm("{ .reg .u64 t; cvta.to.shared.u64 t, %1; cvt.u32.u64 %0, t; }"
        : "=r"(a) : "l"(p));
    return a;
}

// One CTA per 32KB chunk of one (b,n) plane. Zero the smem buffer, write any
// 6x6 blurred-patch cells that fall inside this chunk, then stream it to
// global with a single cp.async.bulk (async-proxy stores: ~5.7 TB/s measured,
// vs ~2.2 TB/s for the STG path). Small work quantum -> short per-CTA TMA
// chain (~0.6us) and <=4% load imbalance across SMs.
__global__ void __launch_bounds__(TPB) inver_interp_bulk3(
    const float* __restrict__ Xg,
    const float* __restrict__ kp,
    const float* __restrict__ gk,
    float* __restrict__ out,
    int N, int H, int W, int HW)
{
    __shared__ float buf[CHUNK_FLOATS];   // 32 KB

    const int b     = blockIdx.z;
    const int row   = b * N + blockIdx.y;
    const int chunk = blockIdx.x;
    const int t     = threadIdx.x;
    const int lane  = t & 31;

    const int cbase = chunk * CHUNK_FLOATS;
    const int cfl   = min(CHUNK_FLOATS, HW - cbase);

    // ---- per-warp ballot prologue (Xg row is one-hot or all-zero) ----
    const unsigned FULL = 0xffffffffu;
    float xg = 0.f, kxv = 0.f, kyv = 0.f;
    if (lane < N) {
        xg = Xg[(size_t)row * N + lane];
        const float2 k2 = ((const float2*)kp)[(size_t)b * N + lane];
        kxv = k2.x; kyv = k2.y;
    }
    const unsigned bal = __ballot_sync(FULL, xg != 0.f);
    const bool valid = (bal != 0u);
    const int  j  = valid ? (__ffs(bal) - 1) : 0;
    const float mx = __shfl_sync(FULL, xg,  j);          // mask (0/1)
    const float kx = __shfl_sync(FULL, kxv, j) * mx;
    const float ky = __shfl_sync(FULL, kyv, j) * mx;

    int x0 = 0, y0 = 0, ox1 = 0, oy1 = 0;
    float upx = 0.f, lwx = 0.f, upy = 0.f, lwy = 0.f;
    if (valid) {
        const float x = kx * (1.0f / IM_FE_RATIO) - 0.5f;
        const float y = ky * (1.0f / IM_FE_RATIO) - 0.5f;
        const float maxx = (float)(W - 1);
        const float maxy = (float)(H - 1);
        const float lox = fminf(fmaxf(floorf(x), 0.0f), maxx);
        const float hix = fminf(fmaxf(ceilf(x),  0.0f), maxx);
        const float loy = fminf(fmaxf(floorf(y), 0.0f), maxy);
        const float hiy = fminf(fmaxf(ceilf(y),  0.0f), maxy);
        x0 = (int)lox; y0 = (int)loy;
        ox1 = (int)hix - x0; oy1 = (int)hiy - y0;
        upx = x - lox; lwx = 1.0f - upx;
        upy = y - loy; lwy = 1.0f - upy;
    }

    // ---- zero the buffer ----
    #pragma unroll
    for (int i = t * 4; i < CHUNK_FLOATS; i += TPB * 4)
        *(float4*)(buf + i) = make_float4(0.f, 0.f, 0.f, 0.f);
    __syncthreads();

    // ---- patch cells that land in this chunk (one cell per thread t<36) ----
    if (valid && t < 36) {
        const int dy = t / 6, dx = t - dy * 6;
        const int py = y0 - 2 + dy, px = x0 - 2 + dx;
        if (py >= 0 && py < H && px >= 0 && px < W) {
            const int idx = py * W + px;
            if (idx >= cbase && idx < cbase + cfl) {
                float val = 0.f;
                #pragma unroll
                for (int cy = 0; cy < 2; cy++) {
                    const int   oy = cy ? oy1 : 0;
                    const float wy = cy ? upy : lwy;
                    const int   ki = dy - oy;
                    if (ki < 0 || ki > 4) continue;
                    #pragma unroll
                    for (int cx = 0; cx < 2; cx++) {
                        const int   ox = cx ? ox1 : 0;
                        const float wx = cx ? upx : lwx;
                        const int   kj = dx - ox;
                        if (kj < 0 || kj > 4) continue;
                        val += (wy * wx) * __ldg(gk + ki * 5 + kj);
                    }
                }
                buf[idx - cbase] = val;      // mask==1 when valid
            }
        }
    }
    __syncthreads();

    // ---- single bulk copy to global ----
    float* __restrict__ dst = out + (size_t)row * HW + cbase;
    const int cbytes = cfl * 4;
    if ((cbytes & 15) == 0) {
        if (t == 0) {
            asm volatile("fence.proxy.async.shared::cta;" ::: "memory");
            asm volatile(
                "cp.async.bulk.global.shared::cta.bulk_group [%0], [%1], %2;"
                :: "l"(dst), "r"(smem_u32(buf)), "r"((uint32_t)cbytes)
                : "memory");
            asm volatile("cp.async.bulk.commit_group;" ::: "memory");
            asm volatile("cp.async.bulk.wait_group.read 0;" ::: "memory");
        }
        __syncthreads();   // smem must outlive the async read for all threads
    } else {
        // generality fallback: tail chunk not 16B-multiple -> plain stores
        for (int i = t; i < cfl; i += TPB) dst[i] = buf[i];
    }
}

extern "C" void kernel_launch(void* const* d_in, const int* in_sizes, int n_in,
                              void* d_out, int out_size) {
    const float* Xg = (const float*)d_in[0];   // (B, N, N)
    const float* kp = (const float*)d_in[1];   // (B, N, 2)
    const float* gk = (const float*)d_in[2];   // (N, 1, 5, 5)

    const int rows = in_sizes[1] / 2;          // B*N
    const int N    = in_sizes[0] / rows;       // N (square one-hot)
    const int B    = rows / N;
    const int HW   = out_size / rows;          // H*W
    int W = (int)(sqrt((double)HW) + 0.5);
    int H = HW / W;

    const int chunksPerPlane = (HW + CHUNK_FLOATS - 1) / CHUNK_FLOATS;
    dim3 grid(chunksPerPlane, N, B);

    inver_interp_bulk3<<<grid, TPB>>>(Xg, kp, gk, (float*)d_out, N, H, W, HW);
}